// round 3
// baseline (speedup 1.0000x reference)
#include <cuda_runtime.h>
#include <stdint.h>

#define IN_DIM 16384
#define HID    128
#define ALLN   200000
#define NODES  2000
#define SEG    100
#define NSAMP  128

// Output layout (float32):
//   [0, 256000)            positions[s][n]  (s-major)
//   [256000, 256128)       log_softmax[s]
//   [256128, 456128)       scores[0..200000)
#define OFF_LOGSM (NSAMP * NODES)
#define OFF_SCORES (NSAMP * NODES + NSAMP)

// ---------------- device scratch (no allocation allowed) ----------------
__device__ float g_hacc[HID];
__device__ float g_rowmax[NODES];
__device__ float g_rowlsum[NODES];

// ---------------- XLA f32 tanh (Eigen-style rational approx) ----------------
__device__ __forceinline__ float tanh_xla(float x) {
    float ax = fabsf(x);
    if (ax < 0.0004f) return x;
    float xc = fminf(fmaxf(x, -9.0f), 9.0f);
    float x2 = xc * xc;
    float np = fmaf(x2, -2.76076847742355e-16f, 2.00018790482477e-13f);
    np = fmaf(x2, np, -8.60467152213735e-11f);
    np = fmaf(x2, np, 5.12229709037114e-08f);
    np = fmaf(x2, np, 1.48572235717979e-05f);
    np = fmaf(x2, np, 6.37261928875436e-04f);
    np = fmaf(x2, np, 4.89352455891786e-03f);
    np = np * xc;
    float dp = fmaf(x2, 1.19825839466702e-06f, 1.18534705686654e-04f);
    dp = fmaf(x2, dp, 2.26843463243900e-03f);
    dp = fmaf(x2, dp, 4.89352518554385e-03f);
    return np / dp;
}

// ---------------- threefry2x32, key=(0,42), counts=(0, i) --------------------
// Partitionable JAX scheme, 32-bit: bits[i] = out0 ^ out1.
__device__ __forceinline__ unsigned tf_xor(unsigned ctr) {
    const unsigned K0 = 0u;
    const unsigned K1 = 42u;
    const unsigned K2 = 0u ^ 42u ^ 0x1BD11BDAu;
    unsigned x0 = 0u + K0;     // counts_hi = 0
    unsigned x1 = ctr + K1;    // counts_lo = i
#define TFR(r) { x0 += x1; x1 = __funnelshift_l(x1, x1, (r)); x1 ^= x0; }
    TFR(13) TFR(15) TFR(26) TFR(6)
    x0 += K1; x1 += K2 + 1u;
    TFR(17) TFR(29) TFR(16) TFR(24)
    x0 += K2; x1 += K0 + 2u;
    TFR(13) TFR(15) TFR(26) TFR(6)
    x0 += K0; x1 += K1 + 3u;
    TFR(17) TFR(29) TFR(16) TFR(24)
    x0 += K1; x1 += K2 + 4u;
    TFR(13) TFR(15) TFR(26) TFR(6)
    x0 += K2; x1 += K0 + 5u;
#undef TFR
    return x0 ^ x1;
}

// ---------------- K0: zero scratch + log_softmax output region ---------------
__global__ void k_init(float* out) {
    int t = threadIdx.x;
    if (t < HID)   g_hacc[t] = 0.0f;
    if (t < NSAMP) out[OFF_LOGSM + t] = 0.0f;
}

// ---------------- K1: partial accumulation of x @ W1 (pre-tanh) -------------
__global__ void k_h_partial(const float* __restrict__ x, const float* __restrict__ W1) {
    __shared__ float sm[256];
    int t = threadIdx.x;
    int j = t & 127;
    int half = t >> 7;
    int i0 = blockIdx.x * 128 + half * 64;
    float acc = 0.0f;
#pragma unroll 8
    for (int ii = 0; ii < 64; ii++) {
        int i = i0 + ii;
        acc = fmaf(x[i], W1[i * HID + j], acc);  // coalesced across j
    }
    sm[t] = acc;
    __syncthreads();
    if (t < 128) atomicAdd(&g_hacc[j], sm[t] + sm[t + 128]);
}

// ---------------- K2: scores = 10 * tanh(h @ W2 + b2) ------------------------
__global__ void k_scores(const float* __restrict__ W2, const float* __restrict__ b1,
                         const float* __restrict__ b2, float* __restrict__ out) {
    __shared__ float hs[HID];
    int t = threadIdx.x;
    if (t < HID) hs[t] = tanh_xla(g_hacc[t] + b1[t]);
    __syncthreads();
    int col = blockIdx.x * 256 + t;
    if (col < ALLN) {
        float acc = b2[col];
#pragma unroll 8
        for (int k = 0; k < HID; k++)
            acc = fmaf(hs[k], W2[(size_t)k * ALLN + col], acc);  // coalesced
        out[OFF_SCORES + col] = 10.0f * tanh_xla(acc);
    }
}

// ---------------- K3: per-node row max + log(sum(exp(shifted))) --------------
__global__ void k_rowstats(const float* __restrict__ out) {
    int gw = (blockIdx.x * blockDim.x + threadIdx.x) >> 5;
    int lane = threadIdx.x & 31;
    if (gw >= NODES) return;
    const float* row = out + OFF_SCORES + gw * SEG;
    float vals[4];
    int cnt = 0;
#pragma unroll
    for (int t = 0; t < 4; t++) {
        int k = lane + t * 32;
        if (k < SEG) vals[cnt++] = row[k];
    }
    float m = -__int_as_float(0x7f800000);
    for (int t = 0; t < cnt; t++) m = fmaxf(m, vals[t]);
#pragma unroll
    for (int off = 16; off > 0; off >>= 1)
        m = fmaxf(m, __shfl_xor_sync(0xffffffffu, m, off));
    float s = 0.0f;
    for (int t = 0; t < cnt; t++) s += expf(vals[t] - m);
#pragma unroll
    for (int off = 16; off > 0; off >>= 1)
        s += __shfl_xor_sync(0xffffffffu, s, off);
    if (lane == 0) {
        g_rowmax[gw] = m;
        g_rowlsum[gw] = logf(s);
    }
}

// ---------------- K4: gumbel-max sampling + log-prob accumulation ------------
// one warp per (s, n); 256000 warps total
__global__ void k_sample(float* __restrict__ out) {
    int wg = (blockIdx.x * blockDim.x + threadIdx.x) >> 5;
    int lane = threadIdx.x & 31;
    int s = wg / NODES;
    int n = wg - s * NODES;
    const float* row = out + OFF_SCORES + n * SEG;
    unsigned base = (unsigned)wg * (unsigned)SEG;  // flat gumbel index of k=0

    float best = -__int_as_float(0x7f800000);
    int bk = 0;
#pragma unroll
    for (int t = 0; t < 4; t++) {
        int k = lane + t * 32;
        if (k < SEG) {
            unsigned b = tf_xor(base + (unsigned)k);
            float f = __uint_as_float((b >> 9) | 0x3f800000u) - 1.0f;
            float u = fmaxf(f, 1.17549435e-38f);
            float g = -logf(-logf(u));
            float v = g + row[k];
            if (v > best) { best = v; bk = k; }  // k increasing -> first occurrence
        }
    }
#pragma unroll
    for (int off = 16; off > 0; off >>= 1) {
        float ov = __shfl_xor_sync(0xffffffffu, best, off);
        int   ok = __shfl_xor_sync(0xffffffffu, bk, off);
        if (ov > best || (ov == best && ok < bk)) { best = ov; bk = ok; }
    }
    if (lane == 0) {
        out[s * NODES + n] = (float)bk;
        float lp = (row[bk] - g_rowmax[n]) - g_rowlsum[n];
        atomicAdd(&out[OFF_LOGSM + s], lp);
    }
}

// ---------------- launch ----------------
extern "C" void kernel_launch(void* const* d_in, const int* in_sizes, int n_in,
                              void* d_out, int out_size) {
    const float* x  = (const float*)d_in[0];
    const float* W1 = (const float*)d_in[1];
    const float* b1 = (const float*)d_in[2];
    const float* W2 = (const float*)d_in[3];
    const float* b2 = (const float*)d_in[4];
    float* out = (float*)d_out;

    k_init<<<1, 256>>>(out);
    k_h_partial<<<IN_DIM / 128, 256>>>(x, W1);
    k_scores<<<(ALLN + 255) / 256, 256>>>(W2, b1, b2, out);
    k_rowstats<<<(NODES * 32 + 255) / 256, 256>>>(out);
    k_sample<<<(NSAMP * NODES * 32) / 256, 256>>>(out);
}

// round 4
// speedup vs baseline: 2.2190x; 2.2190x over previous
#include <cuda_runtime.h>
#include <stdint.h>

#define IN_DIM 16384
#define HID    128
#define ALLN   200000
#define NODES  2000
#define SEG    100
#define NSAMP  128

// Output layout (float32):
//   [0, 256000)            positions[s][n]  (s-major)
//   [256000, 256128)       log_softmax[s]
//   [256128, 456128)       scores[0..200000)
#define OFF_LOGSM (NSAMP * NODES)
#define OFF_SCORES (NSAMP * NODES + NSAMP)

// ---------------- device scratch (no allocation allowed) ----------------
__device__ float g_hacc[HID];
__device__ float g_rowmax[NODES];
__device__ float g_rowlsum[NODES];

// ---------------- XLA f32 tanh (Eigen-style rational approx) ----------------
__device__ __forceinline__ float tanh_xla(float x) {
    float ax = fabsf(x);
    if (ax < 0.0004f) return x;
    float xc = fminf(fmaxf(x, -9.0f), 9.0f);
    float x2 = xc * xc;
    float np = fmaf(x2, -2.76076847742355e-16f, 2.00018790482477e-13f);
    np = fmaf(x2, np, -8.60467152213735e-11f);
    np = fmaf(x2, np, 5.12229709037114e-08f);
    np = fmaf(x2, np, 1.48572235717979e-05f);
    np = fmaf(x2, np, 6.37261928875436e-04f);
    np = fmaf(x2, np, 4.89352455891786e-03f);
    np = np * xc;
    float dp = fmaf(x2, 1.19825839466702e-06f, 1.18534705686654e-04f);
    dp = fmaf(x2, dp, 2.26843463243900e-03f);
    dp = fmaf(x2, dp, 4.89352518554385e-03f);
    return np / dp;
}

// ---------------- threefry2x32, key=(0,42), counts=(0, i) --------------------
// Partitionable JAX scheme, 32-bit: bits[i] = out0 ^ out1.
__device__ __forceinline__ unsigned tf_xor(unsigned ctr) {
    const unsigned K0 = 0u;
    const unsigned K1 = 42u;
    const unsigned K2 = 0u ^ 42u ^ 0x1BD11BDAu;
    unsigned x0 = 0u + K0;     // counts_hi = 0
    unsigned x1 = ctr + K1;    // counts_lo = i
#define TFR(r) { x0 += x1; x1 = __funnelshift_l(x1, x1, (r)); x1 ^= x0; }
    TFR(13) TFR(15) TFR(26) TFR(6)
    x0 += K1; x1 += K2 + 1u;
    TFR(17) TFR(29) TFR(16) TFR(24)
    x0 += K2; x1 += K0 + 2u;
    TFR(13) TFR(15) TFR(26) TFR(6)
    x0 += K0; x1 += K1 + 3u;
    TFR(17) TFR(29) TFR(16) TFR(24)
    x0 += K1; x1 += K2 + 4u;
    TFR(13) TFR(15) TFR(26) TFR(6)
    x0 += K2; x1 += K0 + 5u;
#undef TFR
    return x0 ^ x1;
}

// ---------------- K0: zero scratch + log_softmax output region ---------------
__global__ void k_init(float* out) {
    int t = threadIdx.x;
    if (t < HID)   g_hacc[t] = 0.0f;
    if (t < NSAMP) out[OFF_LOGSM + t] = 0.0f;
}

// ---------------- K1: partial accumulation of x @ W1 (pre-tanh) -------------
__global__ void k_h_partial(const float* __restrict__ x, const float* __restrict__ W1) {
    __shared__ float sm[256];
    int t = threadIdx.x;
    int j = t & 127;
    int half = t >> 7;
    int i0 = blockIdx.x * 128 + half * 64;
    float acc = 0.0f;
#pragma unroll 8
    for (int ii = 0; ii < 64; ii++) {
        int i = i0 + ii;
        acc = fmaf(x[i], W1[i * HID + j], acc);  // coalesced across j
    }
    sm[t] = acc;
    __syncthreads();
    if (t < 128) atomicAdd(&g_hacc[j], sm[t] + sm[t + 128]);
}

// ---------------- K2: scores = 10 * tanh(h @ W2 + b2), 4 cols/thread --------
__global__ void k_scores(const float* __restrict__ W2, const float* __restrict__ b1,
                         const float* __restrict__ b2, float* __restrict__ out) {
    __shared__ float hs[HID];
    int t = threadIdx.x;
    if (t < HID) hs[t] = tanh_xla(g_hacc[t] + b1[t]);
    __syncthreads();
    int col = (blockIdx.x * 256 + t) * 4;
    if (col < ALLN) {
        const float4* b2v = (const float4*)(b2 + col);
        float4 acc = *b2v;
#pragma unroll 8
        for (int k = 0; k < HID; k++) {
            float hk = hs[k];
            float4 w = *(const float4*)(W2 + (size_t)k * ALLN + col);
            acc.x = fmaf(hk, w.x, acc.x);
            acc.y = fmaf(hk, w.y, acc.y);
            acc.z = fmaf(hk, w.z, acc.z);
            acc.w = fmaf(hk, w.w, acc.w);
        }
        float4 r;
        r.x = 10.0f * tanh_xla(acc.x);
        r.y = 10.0f * tanh_xla(acc.y);
        r.z = 10.0f * tanh_xla(acc.z);
        r.w = 10.0f * tanh_xla(acc.w);
        *(float4*)(out + OFF_SCORES + col) = r;
    }
}

// ---------------- K3: per-node row max + log(sum(exp(shifted))) --------------
__global__ void k_rowstats(const float* __restrict__ out) {
    int gw = (blockIdx.x * blockDim.x + threadIdx.x) >> 5;
    int lane = threadIdx.x & 31;
    if (gw >= NODES) return;
    const float* row = out + OFF_SCORES + gw * SEG;
    float vals[4];
    int cnt = 0;
#pragma unroll
    for (int t = 0; t < 4; t++) {
        int k = lane + t * 32;
        if (k < SEG) vals[cnt++] = row[k];
    }
    float m = -__int_as_float(0x7f800000);
    for (int t = 0; t < cnt; t++) m = fmaxf(m, vals[t]);
#pragma unroll
    for (int off = 16; off > 0; off >>= 1)
        m = fmaxf(m, __shfl_xor_sync(0xffffffffu, m, off));
    float s = 0.0f;
    for (int t = 0; t < cnt; t++) s += expf(vals[t] - m);
#pragma unroll
    for (int off = 16; off > 0; off >>= 1)
        s += __shfl_xor_sync(0xffffffffu, s, off);
    if (lane == 0) {
        g_rowmax[gw] = m;
        g_rowlsum[gw] = logf(s);
    }
}

// ---------------- K4: gumbel-max sampling, thread per (s, n) -----------------
// grid = 2000 blocks (one node each), 128 threads (one sample each).
__global__ void __launch_bounds__(128) k_sample(float* __restrict__ out) {
    __shared__ float srow[SEG];
    __shared__ float sstat[2];
    int n = blockIdx.x;
    int s = threadIdx.x;
    const float* row = out + OFF_SCORES + n * SEG;
    if (s < SEG) srow[s] = row[s];
    if (s == 126) sstat[0] = g_rowmax[n];
    if (s == 127) sstat[1] = g_rowlsum[n];
    __syncthreads();

    unsigned base = (unsigned)s * (unsigned)(NODES * SEG) + (unsigned)n * (unsigned)SEG;
    float best = -__int_as_float(0x7f800000);
    int bk = 0;
#pragma unroll 4
    for (int k = 0; k < SEG; k++) {
        unsigned b = tf_xor(base + (unsigned)k);
        float f = __uint_as_float((b >> 9) | 0x3f800000u) - 1.0f;
        float u = fmaxf(f, 1.17549435e-38f);
        float g = -logf(-logf(u));
        float v = g + srow[k];
        if (v > best) { best = v; bk = k; }  // k increasing -> first occurrence
    }
    out[s * NODES + n] = (float)bk;
    float lp = (srow[bk] - sstat[0]) - sstat[1];
    atomicAdd(&out[OFF_LOGSM + s], lp);
}

// ---------------- launch ----------------
extern "C" void kernel_launch(void* const* d_in, const int* in_sizes, int n_in,
                              void* d_out, int out_size) {
    const float* x  = (const float*)d_in[0];
    const float* W1 = (const float*)d_in[1];
    const float* b1 = (const float*)d_in[2];
    const float* W2 = (const float*)d_in[3];
    const float* b2 = (const float*)d_in[4];
    float* out = (float*)d_out;

    k_init<<<1, 256>>>(out);
    k_h_partial<<<IN_DIM / 128, 256>>>(x, W1);
    k_scores<<<(ALLN / 4 + 255) / 256, 256>>>(W2, b1, b2, out);
    k_rowstats<<<(NODES * 32 + 255) / 256, 256>>>(out);
    k_sample<<<NODES, 128>>>(out);
}

// round 5
// speedup vs baseline: 2.5801x; 1.1628x over previous
#include <cuda_runtime.h>
#include <stdint.h>

#define IN_DIM 16384
#define HID    128
#define ALLN   200000
#define NODES  2000
#define SEG    100
#define NSAMP  128

// Output layout (float32):
//   [0, 256000)            positions[s][n]  (s-major)
//   [256000, 256128)       log_softmax[s]
//   [256128, 456128)       scores[0..200000)
#define OFF_LOGSM (NSAMP * NODES)
#define OFF_SCORES (NSAMP * NODES + NSAMP)

__device__ float g_hacc[HID];

// ---------------- XLA f32 tanh (Eigen-style rational approx) ----------------
__device__ __forceinline__ float tanh_xla(float x) {
    float ax = fabsf(x);
    if (ax < 0.0004f) return x;
    float xc = fminf(fmaxf(x, -9.0f), 9.0f);
    float x2 = xc * xc;
    float np = fmaf(x2, -2.76076847742355e-16f, 2.00018790482477e-13f);
    np = fmaf(x2, np, -8.60467152213735e-11f);
    np = fmaf(x2, np, 5.12229709037114e-08f);
    np = fmaf(x2, np, 1.48572235717979e-05f);
    np = fmaf(x2, np, 6.37261928875436e-04f);
    np = fmaf(x2, np, 4.89352455891786e-03f);
    np = np * xc;
    float dp = fmaf(x2, 1.19825839466702e-06f, 1.18534705686654e-04f);
    dp = fmaf(x2, dp, 2.26843463243900e-03f);
    dp = fmaf(x2, dp, 4.89352518554385e-03f);
    return np / dp;
}

// ---------------- threefry2x32, key=(0,42), counts=(0, i) --------------------
// Partitionable JAX scheme, 32-bit: bits[i] = out0 ^ out1.
__device__ __forceinline__ unsigned tf_xor(unsigned ctr) {
    const unsigned K0 = 0u;
    const unsigned K1 = 42u;
    const unsigned K2 = 0u ^ 42u ^ 0x1BD11BDAu;
    unsigned x0 = 0u + K0;
    unsigned x1 = ctr + K1;
#define TFR(r) { x0 += x1; x1 = __funnelshift_l(x1, x1, (r)); x1 ^= x0; }
    TFR(13) TFR(15) TFR(26) TFR(6)
    x0 += K1; x1 += K2 + 1u;
    TFR(17) TFR(29) TFR(16) TFR(24)
    x0 += K2; x1 += K0 + 2u;
    TFR(13) TFR(15) TFR(26) TFR(6)
    x0 += K0; x1 += K1 + 3u;
    TFR(17) TFR(29) TFR(16) TFR(24)
    x0 += K1; x1 += K2 + 4u;
    TFR(13) TFR(15) TFR(26) TFR(6)
    x0 += K2; x1 += K0 + 5u;
#undef TFR
    return x0 ^ x1;
}

// Exact JAX gumbel+score value for index ctr (precise path, used for top-2 only)
__device__ __forceinline__ float precise_v(unsigned ctr, float rowk) {
    unsigned b = tf_xor(ctr);
    float f = __uint_as_float((b >> 9) | 0x3f800000u) - 1.0f;
    float u = fmaxf(f, 1.17549435e-38f);
    return -logf(-logf(u)) + rowk;
}

// ---------------- K0: zero scratch + log_softmax output region ---------------
__global__ void k_init(float* out) {
    int t = threadIdx.x;
    if (t < HID)   g_hacc[t] = 0.0f;
    if (t < NSAMP) out[OFF_LOGSM + t] = 0.0f;
}

// ---------------- K1: partial accumulation of x @ W1 (pre-tanh) -------------
__global__ void k_h_partial(const float* __restrict__ x, const float* __restrict__ W1) {
    __shared__ float sm[256];
    int t = threadIdx.x;
    int j = t & 127;
    int half = t >> 7;
    int i0 = blockIdx.x * 128 + half * 64;
    float acc = 0.0f;
#pragma unroll 8
    for (int ii = 0; ii < 64; ii++) {
        int i = i0 + ii;
        acc = fmaf(x[i], W1[i * HID + j], acc);
    }
    sm[t] = acc;
    __syncthreads();
    if (t < 128) atomicAdd(&g_hacc[j], sm[t] + sm[t + 128]);
}

// ---------------- K2 fused: scores + rowstats + gumbel sampling --------------
// block = node n (2000 blocks x 128 threads); thread t = sample s in sampling phase
__global__ void __launch_bounds__(128) k_fused(const float* __restrict__ W2,
                                               const float* __restrict__ b1,
                                               const float* __restrict__ b2,
                                               float* __restrict__ out) {
    __shared__ float hs[HID];
    __shared__ float srow[SEG];
    __shared__ float sexp[SEG];   // exp(-srow[k]) for fast argmin compare
    __shared__ float red[8];
    __shared__ float sstat[2];    // rowmax, log(sumexp)
    const int n = blockIdx.x;
    const int t = threadIdx.x;
    const float NEGINF = -__int_as_float(0x7f800000);
    const float POSINF =  __int_as_float(0x7f800000);

    hs[t] = tanh_xla(g_hacc[t] + b1[t]);
    __syncthreads();

    // --- scores for this node's 100 columns (coalesced over t) ---
    if (t < SEG) {
        int col = n * SEG + t;
        float acc = b2[col];
#pragma unroll 8
        for (int k = 0; k < HID; k++)
            acc = fmaf(hs[k], W2[(size_t)k * ALLN + col], acc);
        float sc = 10.0f * tanh_xla(acc);
        srow[t] = sc;
        sexp[t] = expf(-sc);
        out[OFF_SCORES + col] = sc;
    }
    __syncthreads();

    // --- in-block rowmax ---
    float v = (t < SEG) ? srow[t] : NEGINF;
#pragma unroll
    for (int off = 16; off > 0; off >>= 1)
        v = fmaxf(v, __shfl_xor_sync(0xffffffffu, v, off));
    if ((t & 31) == 0) red[t >> 5] = v;
    __syncthreads();
    if (t == 0) sstat[0] = fmaxf(fmaxf(red[0], red[1]), fmaxf(red[2], red[3]));
    __syncthreads();

    // --- in-block log(sum(exp(x - max))) ---
    float e = (t < SEG) ? expf(srow[t] - sstat[0]) : 0.0f;
#pragma unroll
    for (int off = 16; off > 0; off >>= 1)
        e += __shfl_xor_sync(0xffffffffu, e, off);
    if ((t & 31) == 0) red[4 + (t >> 5)] = e;
    __syncthreads();
    if (t == 0) sstat[1] = logf((red[4] + red[5]) + (red[6] + red[7]));
    __syncthreads();

    // --- sampling: thread t = sample s ---
    // argmax_k (gumbel_k + row_k) == argmin_k (-log u_k) * exp(-row_k)
    unsigned base = (unsigned)t * (unsigned)(NODES * SEG) + (unsigned)n * (unsigned)SEG;
    float m1 = POSINF, m2 = POSINF;
    int k1 = 0, k2 = 0;
#pragma unroll 4
    for (int k = 0; k < SEG; k++) {
        unsigned b = tf_xor(base + (unsigned)k);
        float f = __uint_as_float((b >> 9) | 0x3f800000u) - 1.0f;
        float u = fmaxf(f, 1.17549435e-38f);
        float nl = -logf(u);               // one precise logf (fast path)
        float m = nl * sexp[k];
        if (m < m1) { m2 = m1; k2 = k1; m1 = m; k1 = k; }
        else if (m < m2) { m2 = m; k2 = k; }
    }
    // resolve top-2 with the exact JAX expression (handles all rounding races)
    float v1 = precise_v(base + (unsigned)k1, srow[k1]);
    float v2 = precise_v(base + (unsigned)k2, srow[k2]);
    int bk = (v2 > v1 || (v2 == v1 && k2 < k1)) ? k2 : k1;

    out[t * NODES + n] = (float)bk;
    float lp = (srow[bk] - sstat[0]) - sstat[1];
    atomicAdd(&out[OFF_LOGSM + t], lp);
}

// ---------------- launch ----------------
extern "C" void kernel_launch(void* const* d_in, const int* in_sizes, int n_in,
                              void* d_out, int out_size) {
    const float* x  = (const float*)d_in[0];
    const float* W1 = (const float*)d_in[1];
    const float* b1 = (const float*)d_in[2];
    const float* W2 = (const float*)d_in[3];
    const float* b2 = (const float*)d_in[4];
    float* out = (float*)d_out;

    k_init<<<1, 256>>>(out);
    k_h_partial<<<IN_DIM / 128, 256>>>(x, W1);
    k_fused<<<NODES, 128>>>(W2, b1, b2, out);
}